// round 4
// baseline (speedup 1.0000x reference)
#include <cuda_runtime.h>
#include <math.h>
#include <math_constants.h>

#define N_TOK 4096
#define DMODEL 256
#define NHEAD 4
#define DHEAD 64
#define TOPK 30
#define SCALE 0.25f
#define LN_EPS 1e-5f
#define CAP 128

typedef unsigned long long ull;

// ---------------- scratch ----------------------------------------------------------
__device__ float g_q[N_TOK * DMODEL];
__device__ float g_k[N_TOK * DMODEL];
__device__ float g_v[N_TOK * DMODEL];
__device__ float g_ctx[N_TOK * DMODEL];
__device__ float g_resid[N_TOK * DMODEL];

// ---------------- helpers -----------------------------------------------------------
__device__ __forceinline__ void fma2(ull& d, ull a, ull b) {
    asm("fma.rn.f32x2 %0, %1, %2, %0;" : "+l"(d) : "l"(a), "l"(b));
}
__device__ __forceinline__ float2 unpack2(ull v) {
    float2 f;
    asm("mov.b64 {%0, %1}, %2;" : "=f"(f.x), "=f"(f.y) : "l"(v));
    return f;
}
__device__ __forceinline__ unsigned ford(float f) {  // monotone float->uint
    unsigned u = __float_as_uint(f);
    return (u & 0x80000000u) ? ~u : (u | 0x80000000u);
}
__device__ __forceinline__ float unford(unsigned u) {
    return __uint_as_float((u & 0x80000000u) ? (u & 0x7FFFFFFFu) : ~u);
}

// ---- warp bitonic sort: 128 ull keys, 4 per lane, DESCENDING ----------------------
__device__ __forceinline__ void bitonic128(ull k[4], int lane) {
#pragma unroll
    for (int size = 2; size <= 128; size <<= 1) {
#pragma unroll
        for (int stride = 64; stride >= 4; stride >>= 1) {
            if (stride < size || (stride == 64 && size == 128)) {
                if (stride <= (size >> 1) || size == 128) {
                    // guarded below properly
                }
            }
            if (stride > (size >> 1)) continue;
#pragma unroll
            for (int r = 0; r < 4; ++r) {
                int e = (lane << 2) | r;
                ull other = __shfl_xor_sync(0xFFFFFFFFu, k[r], stride >> 2);
                bool desc = ((e & size) == 0);
                bool lower = ((e & stride) == 0);
                bool takemax = (lower == desc);
                ull mx = (k[r] > other) ? k[r] : other;
                ull mn = (k[r] > other) ? other : k[r];
                k[r] = takemax ? mx : mn;
            }
        }
        if (size >= 4) {  // stride 2 (in-lane)
#pragma unroll
            for (int r = 0; r < 2; ++r) {
                int e = (lane << 2) | r;
                bool desc = ((e & size) == 0);
                ull a = k[r], b = k[r + 2];
                bool sw = desc ? (a < b) : (a > b);
                if (sw) { k[r] = b; k[r + 2] = a; }
            }
        }
        {  // stride 1 (in-lane)
#pragma unroll
            for (int r = 0; r < 4; r += 2) {
                int e = (lane << 2) | r;
                bool desc = ((e & size) == 0);
                ull a = k[r], b = k[r + 1];
                bool sw = desc ? (a < b) : (a > b);
                if (sw) { k[r] = b; k[r + 1] = a; }
            }
        }
    }
}

// compact a row's candidate buffer to its sorted top-30; update cnt/tau
__device__ __forceinline__ void warp_compact(ull* buf, int& cnt, ull& tau, int lane) {
    __syncwarp();
    ull k[4];
#pragma unroll
    for (int r = 0; r < 4; ++r) {
        int e = (lane << 2) | r;
        k[r] = (e < cnt) ? buf[e] : 0ull;
    }
    bitonic128(k, lane);
#pragma unroll
    for (int r = 0; r < 4; ++r) {
        int e = (lane << 2) | r;
        if (e < TOPK) buf[e] = k[r];
    }
    cnt = TOPK;
    tau = __shfl_sync(0xFFFFFFFFu, k[1], 7);  // element 29 = 30th best
    __syncwarp();
}

// ---------------- 128x64-tile fp32 GEMM: C = A @ B^T (+bias)(+res) ------------------
template <bool ADD_RES>
__device__ __forceinline__ void gemm128_body(const float* __restrict__ A,
                                             const float* __restrict__ B,
                                             const float* __restrict__ bias,
                                             const float* __restrict__ res,
                                             float* __restrict__ C) {
    __shared__ ull As[128 * 32];
    __shared__ ull Bs[64 * 32];
    const int tid = threadIdx.x;
    const int bm = blockIdx.y * 128;
    const int bn = blockIdx.x * 64;
    const int qg = tid >> 4;
    const int kg = tid & 15;

    ull acc[8][4];
#pragma unroll
    for (int a = 0; a < 8; ++a)
#pragma unroll
        for (int b = 0; b < 4; ++b) acc[a][b] = 0ull;

    for (int kk = 0; kk < 256; kk += 64) {
        __syncthreads();
#pragma unroll
        for (int i = 0; i < 16; ++i) {
            int idx = tid + i * 256;
            int r = idx >> 5, c = idx & 31;
            As[(r << 5) | (c ^ (r >> 3))] =
                *(const ull*)(A + (size_t)(bm + r) * 256 + kk + c * 2);
        }
#pragma unroll
        for (int i = 0; i < 8; ++i) {
            int idx = tid + i * 256;
            int r = idx >> 5, c = idx & 31;
            Bs[(r << 5) | (c ^ (r >> 2))] =
                *(const ull*)(B + (size_t)(bn + r) * 256 + kk + c * 2);
        }
        __syncthreads();
#pragma unroll 4
        for (int d2 = 0; d2 < 32; ++d2) {
            ull qv[8], kv[4];
#pragma unroll
            for (int a = 0; a < 8; ++a) qv[a] = As[((qg * 8 + a) << 5) | (d2 ^ qg)];
#pragma unroll
            for (int b = 0; b < 4; ++b) kv[b] = Bs[((kg * 4 + b) << 5) | (d2 ^ kg)];
#pragma unroll
            for (int a = 0; a < 8; ++a)
#pragma unroll
                for (int b = 0; b < 4; ++b) fma2(acc[a][b], qv[a], kv[b]);
        }
    }
    float4 bi = *(const float4*)(bias + bn + kg * 4);
#pragma unroll
    for (int a = 0; a < 8; ++a) {
        int row = bm + qg * 8 + a;
        float2 f0 = unpack2(acc[a][0]);
        float2 f1 = unpack2(acc[a][1]);
        float2 f2 = unpack2(acc[a][2]);
        float2 f3 = unpack2(acc[a][3]);
        float4 o;
        o.x = f0.x + f0.y + bi.x;
        o.y = f1.x + f1.y + bi.y;
        o.z = f2.x + f2.y + bi.z;
        o.w = f3.x + f3.y + bi.w;
        if (ADD_RES) {
            float4 r4 = *(const float4*)(res + (size_t)row * 256 + bn + kg * 4);
            o.x += r4.x; o.y += r4.y; o.z += r4.z; o.w += r4.w;
        }
        *(float4*)(C + (size_t)row * 256 + bn + kg * 4) = o;
    }
}

// ---------------- K1: fused Q/K/V projections ---------------------------------------
__global__ __launch_bounds__(256) void proj_kernel(
    const float* __restrict__ q_in, const float* __restrict__ k_in,
    const float* __restrict__ v_in, const float* __restrict__ Wq,
    const float* __restrict__ bq, const float* __restrict__ Wk,
    const float* __restrict__ bk, const float* __restrict__ Wv,
    const float* __restrict__ bv) {
    const float *A, *B, *bias;
    float* C;
    if (blockIdx.z == 0) { A = q_in; B = Wq; bias = bq; C = g_q; }
    else if (blockIdx.z == 1) { A = k_in; B = Wk; bias = bk; C = g_k; }
    else { A = v_in; B = Wv; bias = bv; C = g_v; }
    gemm128_body<false>(A, B, bias, nullptr, C);
}

// ---------------- K2: fused scores + exact top-30 + softmax + attn + ctx ------------
// grid (32 q-tiles, 4 heads), 512 threads = 16 warps; warp w owns rows w*8..w*8+7.
__global__ __launch_bounds__(512, 1) void attn_fused(float* __restrict__ attn) {
    extern __shared__ char smraw[];
    ull* Qs = (ull*)smraw;                 // [row][d2]    128*32 ull = 32KB
    ull* Ks = Qs + 128 * 32;               // [d2][col^d2] 32*128 ull = 32KB
    ull* cand = Ks + 32 * 128;             // [row][CAP]   128*128 ull = 128KB
    int* rowcnt = (int*)(cand + 128 * CAP);
    ull* rowtau = (ull*)(rowcnt + 128 + 128);  // 8B aligned after 128 ints (+pad)

    const unsigned FULL = 0xFFFFFFFFu;
    const int tid = threadIdx.x;
    const int w = tid >> 5, lane = tid & 31;
    const int h = blockIdx.y;
    const int qb0 = blockIdx.x * 128;

    // load Q tile: Qs[r*32 + c] (broadcast-read later, conflict-free store)
#pragma unroll
    for (int i = 0; i < 8; ++i) {
        int idx = tid + i * 512;
        int r = idx >> 5, c = idx & 31;
        Qs[r * 32 + c] = *(const ull*)(g_q + (size_t)(qb0 + r) * 256 + h * 64 + c * 2);
    }
    if (tid < 128) {
        rowcnt[tid] = 0;
        rowtau[tid] = 0ull;
    }

    // prefetch K tile 0 into registers
    ull kreg[8];
#pragma unroll
    for (int i = 0; i < 8; ++i) {
        int idx = tid + i * 512;
        int r = idx >> 5, c = idx & 31;
        kreg[i] = *(const ull*)(g_k + (size_t)r * 256 + h * 64 + c * 2);
    }

    const ull* qrow = Qs + (w * 8) * 32;

    for (int kt = 0; kt < 32; ++kt) {
        __syncthreads();  // previous tile's Ks reads complete
        // store K tile: Ks[c*128 + (r^c)]  (2-wavefront stores, conflict-free reads)
#pragma unroll
        for (int i = 0; i < 8; ++i) {
            int idx = tid + i * 512;
            int r = idx >> 5, c = idx & 31;
            Ks[c * 128 + (r ^ c)] = kreg[i];
        }
        // issue next tile's loads (in flight during compute)
        if (kt + 1 < 32) {
#pragma unroll
            for (int i = 0; i < 8; ++i) {
                int idx = tid + i * 512;
                int r = idx >> 5, c = idx & 31;
                kreg[i] = *(const ull*)(g_k + (size_t)((kt + 1) * 128 + r) * 256 +
                                        h * 64 + c * 2);
            }
        }
        __syncthreads();

        // GEMM: acc[a][b] = rows w*8+a  x  cols lane+32b
        ull acc[8][4];
#pragma unroll
        for (int a = 0; a < 8; ++a)
#pragma unroll
            for (int b = 0; b < 4; ++b) acc[a][b] = 0ull;
#pragma unroll 4
        for (int d2 = 0; d2 < 32; ++d2) {
            ull kv[4];
#pragma unroll
            for (int b = 0; b < 4; ++b) kv[b] = Ks[d2 * 128 + ((lane + 32 * b) ^ d2)];
#pragma unroll
            for (int a = 0; a < 8; ++a) {
                ull qv = qrow[a * 32 + d2];
#pragma unroll
                for (int b = 0; b < 4; ++b) fma2(acc[a][b], qv, kv[b]);
            }
        }

        // selection: append candidates (key > tau) with periodic exact compaction
#pragma unroll
        for (int a = 0; a < 8; ++a) {
            const int row = w * 8 + a;
            ull key[4];
#pragma unroll
            for (int b = 0; b < 4; ++b) {
                float2 f = unpack2(acc[a][b]);
                float s = (f.x + f.y) * SCALE;
                int col = kt * 128 + lane + 32 * b;
                key[b] = ((ull)ford(s) << 32) | (unsigned)(4095 - col);
            }
            ull tau = rowtau[row];
            int cnt = rowcnt[row];
            ull* cb = cand + row * CAP;
#pragma unroll
            for (int b = 0; b < 4; ++b) {
                bool pred = key[b] > tau;
                unsigned mask = __ballot_sync(FULL, pred);
                int nb = __popc(mask);
                if (cnt + nb > CAP) {
                    warp_compact(cb, cnt, tau, lane);
                    pred = key[b] > tau;
                    mask = __ballot_sync(FULL, pred);
                    nb = __popc(mask);
                }
                if (pred) {
                    int pos = cnt + __popc(mask & ((1u << lane) - 1u));
                    cb[pos] = key[b];
                }
                cnt += nb;
            }
            rowtau[row] = tau;
            rowcnt[row] = cnt;
        }
    }

    // final exact top-30 + softmax; keep (p, idx) in registers per row
    float pk[8];
    int ik[8];
#pragma unroll
    for (int a = 0; a < 8; ++a) {
        const int row = w * 8 + a;
        ull tau = rowtau[row];
        int cnt = rowcnt[row];
        ull* cb = cand + row * CAP;
        warp_compact(cb, cnt, tau, lane);  // sorted desc, top-30 in cb[0..30)
        ull kk = (lane < TOPK) ? cb[lane] : 0ull;
        float v = unford((unsigned)(kk >> 32));
        int ix = 4095 - (int)(kk & 0xFFFFFFFFu);
        float vmax = __shfl_sync(FULL, v, 0);  // sorted: lane 0 is max
        float e = (lane < TOPK) ? expf(v - vmax) : 0.f;
        float s = e;
#pragma unroll
        for (int o = 16; o; o >>= 1) s += __shfl_xor_sync(FULL, s, o);
        pk[a] = e / s;
        ik[a] = ix;
    }
    __syncthreads();

    // zero-fill this block's 128 attn rows (2MB)
    float* arow0 = attn + (size_t)(h * N_TOK + qb0) * N_TOK;
    float4* a4 = (float4*)arow0;
    const float4 z4 = make_float4(0.f, 0.f, 0.f, 0.f);
#pragma unroll 8
    for (int i = tid; i < 128 * (N_TOK / 4); i += 512) a4[i] = z4;
    __syncthreads();

    // scatter probs + sparse ctx (each warp: its 8 rows)
#pragma unroll
    for (int a = 0; a < 8; ++a) {
        const int row = w * 8 + a;
        if (lane < TOPK) arow0[(size_t)row * N_TOK + ik[a]] = pk[a];
        float2 acc2 = make_float2(0.f, 0.f);
        const float* vb = g_v + h * 64 + 2 * lane;
#pragma unroll 6
        for (int j = 0; j < TOPK; ++j) {
            float pj = __shfl_sync(FULL, pk[a], j);
            int ij = __shfl_sync(FULL, ik[a], j);
            float2 vv = *(const float2*)(vb + (size_t)ij * 256);
            acc2.x += pj * vv.x;
            acc2.y += pj * vv.y;
        }
        *(float2*)(g_ctx + (size_t)(qb0 + row) * 256 + h * 64 + 2 * lane) = acc2;
    }
}

// ---------------- K3: out-proj + residual -> g_resid --------------------------------
__global__ __launch_bounds__(256) void oproj_kernel(const float* __restrict__ Wo,
                                                    const float* __restrict__ bo,
                                                    const float* __restrict__ q_in) {
    gemm128_body<true>(g_ctx, Wo, bo, q_in, g_resid);
}

// ---------------- K4: row LayerNorm -> d_out[0 : N*D] -------------------------------
__global__ __launch_bounds__(256) void ln_kernel(const float* __restrict__ g,
                                                 const float* __restrict__ b,
                                                 float* __restrict__ out) {
    const int row = blockIdx.x;
    const int tid = threadIdx.x;
    float x = g_resid[(size_t)row * 256 + tid];
    float s = x, s2 = x * x;
#pragma unroll
    for (int o = 16; o; o >>= 1) {
        s += __shfl_xor_sync(0xFFFFFFFFu, s, o);
        s2 += __shfl_xor_sync(0xFFFFFFFFu, s2, o);
    }
    __shared__ float rs[8], rs2[8];
    const int w = tid >> 5, lane = tid & 31;
    if (lane == 0) { rs[w] = s; rs2[w] = s2; }
    __syncthreads();
    float tot = 0.f, tot2 = 0.f;
#pragma unroll
    for (int i = 0; i < 8; ++i) { tot += rs[i]; tot2 += rs2[i]; }
    float mu = tot * (1.0f / 256.0f);
    float var = tot2 * (1.0f / 256.0f) - mu * mu;
    float inv = rsqrtf(var + LN_EPS);
    out[(size_t)row * 256 + tid] = (x - mu) * inv * g[tid] + b[tid];
}

// ---------------- launch --------------------------------------------------------------
extern "C" void kernel_launch(void* const* d_in, const int* in_sizes, int n_in,
                              void* d_out, int out_size) {
    const float* key_in   = (const float*)d_in[0];
    const float* value_in = (const float*)d_in[1];
    const float* query_in = (const float*)d_in[2];
    const float* Wq = (const float*)d_in[3];
    const float* bq = (const float*)d_in[4];
    const float* Wk = (const float*)d_in[5];
    const float* bk = (const float*)d_in[6];
    const float* Wv = (const float*)d_in[7];
    const float* bv = (const float*)d_in[8];
    const float* Wo = (const float*)d_in[9];
    const float* bo = (const float*)d_in[10];
    const float* ln_g = (const float*)d_in[11];
    const float* ln_b = (const float*)d_in[12];

    float* out = (float*)d_out;
    float* attn = out + (size_t)N_TOK * DMODEL;

    // smem: Qs 32KB + Ks 32KB + cand 128KB + rowcnt (128+128)*4 + rowtau 128*8
    const int ATTN_SMEM = 128 * 32 * 8 + 32 * 128 * 8 + 128 * CAP * 8 +
                          (128 + 128) * 4 + 128 * 8;
    cudaFuncSetAttribute(attn_fused, cudaFuncAttributeMaxDynamicSharedMemorySize,
                         ATTN_SMEM);

    // 1) Q/K/V projections
    proj_kernel<<<dim3(4, 32, 3), 256>>>(query_in, key_in, value_in, Wq, bq, Wk, bk,
                                         Wv, bv);
    // 2) fused scores + exact top-30 + softmax + attn write + sparse ctx
    attn_fused<<<dim3(32, 4), 512, ATTN_SMEM>>>(attn);
    // 3) output projection + residual
    oproj_kernel<<<dim3(4, 32), 256>>>(Wo, bo, query_in);
    // 4) layernorm
    ln_kernel<<<N_TOK, 256>>>(ln_g, ln_b, out);
}

// round 5
// speedup vs baseline: 2.9678x; 2.9678x over previous
#include <cuda_runtime.h>
#include <math.h>
#include <math_constants.h>

#define N_TOK 4096
#define DMODEL 256
#define NHEAD 4
#define DHEAD 64
#define TOPK 30
#define SCALE 0.25f
#define LN_EPS 1e-5f

typedef unsigned long long ull;

// ---------------- scratch (static device allocations; no runtime alloc) ----------
__device__ float g_q[N_TOK * DMODEL];
__device__ float g_k[N_TOK * DMODEL];
__device__ float g_v[N_TOK * DMODEL];
__device__ float g_ctx[N_TOK * DMODEL];
__device__ float g_resid[N_TOK * DMODEL];
__device__ float g_scores[(size_t)NHEAD * N_TOK * N_TOK];  // 256 MB score scratch

// ---------------- packed fp32x2 helpers ------------------------------------------
__device__ __forceinline__ void fma2(ull& d, ull a, ull b) {
    asm("fma.rn.f32x2 %0, %1, %2, %0;" : "+l"(d) : "l"(a), "l"(b));
}
__device__ __forceinline__ float2 unpack2(ull v) {
    float2 f;
    asm("mov.b64 {%0, %1}, %2;" : "=f"(f.x), "=f"(f.y) : "l"(v));
    return f;
}
// monotone float->uint map (ascending)
__device__ __forceinline__ unsigned ford(float f) {
    unsigned u = __float_as_uint(f);
    return (u & 0x80000000u) ? ~u : (u | 0x80000000u);
}

// ---------------- 64x64-tile fp32 GEMM body: C = A @ B^T (+bias)(+res) -----------
template <bool ADD_RES>
__device__ __forceinline__ void gemm64_body(const float* __restrict__ A,
                                            const float* __restrict__ B,
                                            const float* __restrict__ bias,
                                            const float* __restrict__ res,
                                            float* __restrict__ C) {
    __shared__ ull As[64 * 33];
    __shared__ ull Bs[64 * 33];
    const int tid = threadIdx.x;
    const int bm = blockIdx.y * 64;
    const int bn = blockIdx.x * 64;
    const int qg = (tid & 7) | ((tid >> 7) << 3);
    const int kg = (tid >> 3) & 15;

    ull acc[4][4];
#pragma unroll
    for (int a = 0; a < 4; ++a)
#pragma unroll
        for (int b = 0; b < 4; ++b) acc[a][b] = 0ull;

    for (int kk = 0; kk < 256; kk += 64) {
        __syncthreads();
#pragma unroll
        for (int i = 0; i < 8; ++i) {
            int idx = tid + i * 256;
            int r = idx >> 5, c = idx & 31;
            As[r * 33 + c] = *(const ull*)(A + (size_t)(bm + r) * 256 + kk + c * 2);
            Bs[r * 33 + c] = *(const ull*)(B + (size_t)(bn + r) * 256 + kk + c * 2);
        }
        __syncthreads();
#pragma unroll 8
        for (int d2 = 0; d2 < 32; ++d2) {
            ull qv[4], kv[4];
#pragma unroll
            for (int a = 0; a < 4; ++a) qv[a] = As[(qg * 4 + a) * 33 + d2];
#pragma unroll
            for (int b = 0; b < 4; ++b) kv[b] = Bs[(kg * 4 + b) * 33 + d2];
#pragma unroll
            for (int a = 0; a < 4; ++a)
#pragma unroll
                for (int b = 0; b < 4; ++b) fma2(acc[a][b], qv[a], kv[b]);
        }
    }
#pragma unroll
    for (int a = 0; a < 4; ++a) {
        int row = bm + qg * 4 + a;
#pragma unroll
        for (int b = 0; b < 4; ++b) {
            int col = bn + kg * 4 + b;
            float2 f = unpack2(acc[a][b]);
            float v = f.x + f.y + bias[col];
            if (ADD_RES) v += res[(size_t)row * 256 + col];
            C[(size_t)row * 256 + col] = v;
        }
    }
}

// ---------------- K1: fused Q/K/V projections -------------------------------------
__global__ __launch_bounds__(256) void proj_kernel(
    const float* __restrict__ q_in, const float* __restrict__ k_in,
    const float* __restrict__ v_in, const float* __restrict__ Wq,
    const float* __restrict__ bq, const float* __restrict__ Wk,
    const float* __restrict__ bk, const float* __restrict__ Wv,
    const float* __restrict__ bv) {
    const float *A, *B, *bias;
    float* C;
    if (blockIdx.z == 0) { A = q_in; B = Wq; bias = bq; C = g_q; }
    else if (blockIdx.z == 1) { A = k_in; B = Wk; bias = bk; C = g_k; }
    else { A = v_in; B = Wv; bias = bv; C = g_v; }
    gemm64_body<false>(A, B, bias, nullptr, C);
}

// ---------------- K2a: dense score GEMM -> g_scores; zero attn tile ----------------
// grid: (64 kb, 32 qb, 4 h). block 256. tile 128(q) x 64(k). micro 8x4 in ull.
__global__ __launch_bounds__(256, 2) void score_kernel(float* __restrict__ attn) {
    __shared__ ull Qs[128 * 32];
    __shared__ ull Ks[64 * 32];
    const int tid = threadIdx.x;
    const int h = blockIdx.z;
    const int qb0 = blockIdx.y * 128;
    const int kb0 = blockIdx.x * 64;
    const int kg = tid & 15;   // 16 col-groups of 4
    const int qg = tid >> 4;   // 16 row-groups of 8

    // zero-fill this block's attn tile (rows qb0..+128, cols kb0..+64), streaming
    {
        const float4 z4 = make_float4(0.f, 0.f, 0.f, 0.f);
#pragma unroll
        for (int i = 0; i < 8; ++i) {
            int idx = tid + i * 256;
            int r = idx >> 4, c4 = idx & 15;
            __stcs((float4*)(attn + (size_t)(h * N_TOK + qb0 + r) * N_TOK + kb0 +
                             c4 * 4),
                   z4);
        }
    }

    // fill Q tile: 4096 ull, swizzle c ^ (r>>3)
#pragma unroll
    for (int i = 0; i < 16; ++i) {
        int idx = tid + i * 256;
        int r = idx >> 5, c = idx & 31;
        Qs[(r << 5) | (c ^ (r >> 3))] =
            *(const ull*)(g_q + (size_t)(qb0 + r) * 256 + h * 64 + c * 2);
    }
    // fill K tile: 2048 ull, swizzle c ^ (r>>2)
#pragma unroll
    for (int i = 0; i < 8; ++i) {
        int idx = tid + i * 256;
        int r = idx >> 5, c = idx & 31;
        Ks[(r << 5) | (c ^ (r >> 2))] =
            *(const ull*)(g_k + (size_t)(kb0 + r) * 256 + h * 64 + c * 2);
    }
    __syncthreads();

    ull acc[8][4];
#pragma unroll
    for (int a = 0; a < 8; ++a)
#pragma unroll
        for (int b = 0; b < 4; ++b) acc[a][b] = 0ull;

#pragma unroll 4
    for (int d2 = 0; d2 < 32; ++d2) {
        ull qv[8], kv[4];
#pragma unroll
        for (int a = 0; a < 8; ++a) qv[a] = Qs[((qg * 8 + a) << 5) | (d2 ^ qg)];
#pragma unroll
        for (int b = 0; b < 4; ++b) kv[b] = Ks[((kg * 4 + b) << 5) | (d2 ^ kg)];
#pragma unroll
        for (int a = 0; a < 8; ++a)
#pragma unroll
            for (int b = 0; b < 4; ++b) fma2(acc[a][b], qv[a], kv[b]);
    }

#pragma unroll
    for (int a = 0; a < 8; ++a) {
        int row = qb0 + qg * 8 + a;
        float4 o;
        float2 f0 = unpack2(acc[a][0]);
        float2 f1 = unpack2(acc[a][1]);
        float2 f2 = unpack2(acc[a][2]);
        float2 f3 = unpack2(acc[a][3]);
        o.x = (f0.x + f0.y) * SCALE;
        o.y = (f1.x + f1.y) * SCALE;
        o.z = (f2.x + f2.y) * SCALE;
        o.w = (f3.x + f3.y) * SCALE;
        __stcs((float4*)(g_scores + ((size_t)(h * N_TOK + row)) * N_TOK + kb0 +
                         kg * 4),
               o);
    }
}

// ---------------- K2b: warp-per-row top-30 + softmax + scatter + sparse ctx -------
__global__ __launch_bounds__(256) void topk_kernel(float* __restrict__ attn) {
    const unsigned FULL = 0xFFFFFFFFu;
    const int warp = threadIdx.x >> 5, lane = threadIdx.x & 31;
    const int row = blockIdx.x * 8 + warp;  // 0..16383  (= h*4096 + n)
    const int h = row >> 12;
    const int n = row & 4095;
    const float4* p4 = (const float4*)(g_scores + (size_t)row * N_TOK);

    // distributed top-30 list in lanes 0..29
    unsigned lu = 0u;          // ordered-bits value; 0 is below any real score
    int li = 0x7FFFFFFF;
    unsigned wu = 0u;          // current worst (value bits)
    int wi = 0x7FFFFFFF;       // current worst index
    int wslot = 0;             // lane holding the worst

    for (int c = 0; c < 32; ++c) {
        float4 v = __ldcs(p4 + c * 32 + lane);
#pragma unroll
        for (int j = 0; j < 4; ++j) {
            float s = (j == 0) ? v.x : (j == 1) ? v.y : (j == 2) ? v.z : v.w;
            unsigned cu = ford(s);
            int ci = c * 128 + lane * 4 + j;
            unsigned m = __ballot_sync(FULL, (cu > wu) || (cu == wu && ci < wi));
            while (m) {
                int src = __ffs(m) - 1;
                m &= m - 1;
                unsigned c2 = __shfl_sync(FULL, cu, src);
                int i2 = __shfl_sync(FULL, ci, src);
                if ((c2 > wu) || (c2 == wu && i2 < wi)) {
                    if (lane == wslot) { lu = c2; li = i2; }
                    unsigned ku = (lane < TOPK) ? lu : 0xFFFFFFFFu;
                    wu = __reduce_min_sync(FULL, ku);
                    unsigned wim =
                        __reduce_max_sync(FULL, (ku == wu) ? (unsigned)li : 0u);
                    wi = (int)wim;
                    unsigned bs =
                        __ballot_sync(FULL, ku == wu && (unsigned)li == wim);
                    wslot = __ffs(bs) - 1;
                }
            }
        }
    }

    // softmax over the 30 kept scores
    float lv = (lane < TOPK) ? __uint_as_float((lu & 0x80000000u) ? (lu & 0x7FFFFFFFu)
                                                                  : ~lu)
                             : -CUDART_INF_F;
    unsigned mx = __reduce_max_sync(FULL, (lane < TOPK) ? lu : 0u);
    float mval = __uint_as_float((mx & 0x80000000u) ? (mx & 0x7FFFFFFFu) : ~mx);
    float e = (lane < TOPK) ? expf(lv - mval) : 0.f;
    float ssum = e;
#pragma unroll
    for (int o = 16; o; o >>= 1) ssum += __shfl_xor_sync(FULL, ssum, o);
    float p = e / ssum;

    // scatter the 30 probs (row already zeroed by score_kernel)
    float* arow = attn + (size_t)row * N_TOK;
    if (lane < TOPK) arow[li] = p;

    // sparse ctx: ctx[n, h*64 + 2*lane .. +1] = sum_j p_j * V[idx_j]
    float2 acc = make_float2(0.f, 0.f);
    const float* vbase = g_v + h * 64 + 2 * lane;
#pragma unroll 6
    for (int j = 0; j < TOPK; ++j) {
        float pj = __shfl_sync(FULL, p, j);
        int ij = __shfl_sync(FULL, li, j);
        float2 vv = *(const float2*)(vbase + (size_t)ij * 256);
        acc.x += pj * vv.x;
        acc.y += pj * vv.y;
    }
    *(float2*)(g_ctx + (size_t)n * 256 + h * 64 + 2 * lane) = acc;
}

// ---------------- K3: out-proj + residual -> g_resid ------------------------------
__global__ __launch_bounds__(256) void oproj_kernel(const float* __restrict__ Wo,
                                                    const float* __restrict__ bo,
                                                    const float* __restrict__ q_in) {
    gemm64_body<true>(g_ctx, Wo, bo, q_in, g_resid);
}

// ---------------- K4: row LayerNorm -> d_out[0 : N*D] -----------------------------
__global__ __launch_bounds__(256) void ln_kernel(const float* __restrict__ g,
                                                 const float* __restrict__ b,
                                                 float* __restrict__ out) {
    const int row = blockIdx.x;
    const int tid = threadIdx.x;
    float x = g_resid[(size_t)row * 256 + tid];
    float s = x, s2 = x * x;
#pragma unroll
    for (int o = 16; o; o >>= 1) {
        s += __shfl_xor_sync(0xFFFFFFFFu, s, o);
        s2 += __shfl_xor_sync(0xFFFFFFFFu, s2, o);
    }
    __shared__ float rs[8], rs2[8];
    const int w = tid >> 5, lane = tid & 31;
    if (lane == 0) { rs[w] = s; rs2[w] = s2; }
    __syncthreads();
    float tot = 0.f, tot2 = 0.f;
#pragma unroll
    for (int i = 0; i < 8; ++i) { tot += rs[i]; tot2 += rs2[i]; }
    float mu = tot * (1.0f / 256.0f);
    float var = tot2 * (1.0f / 256.0f) - mu * mu;
    float inv = rsqrtf(var + LN_EPS);
    out[(size_t)row * 256 + tid] = (x - mu) * inv * g[tid] + b[tid];
}

// ---------------- launch -----------------------------------------------------------
extern "C" void kernel_launch(void* const* d_in, const int* in_sizes, int n_in,
                              void* d_out, int out_size) {
    const float* key_in   = (const float*)d_in[0];
    const float* value_in = (const float*)d_in[1];
    const float* query_in = (const float*)d_in[2];
    const float* Wq = (const float*)d_in[3];
    const float* bq = (const float*)d_in[4];
    const float* Wk = (const float*)d_in[5];
    const float* bk = (const float*)d_in[6];
    const float* Wv = (const float*)d_in[7];
    const float* bv = (const float*)d_in[8];
    const float* Wo = (const float*)d_in[9];
    const float* bo = (const float*)d_in[10];
    const float* ln_g = (const float*)d_in[11];
    const float* ln_b = (const float*)d_in[12];

    float* out = (float*)d_out;
    float* attn = out + (size_t)N_TOK * DMODEL;

    // 1) Q/K/V projections (64x64 tiles, 768 blocks)
    proj_kernel<<<dim3(4, 64, 3), 256>>>(query_in, key_in, value_in, Wq, bq, Wk, bk,
                                         Wv, bv);
    // 2a) dense scaled scores -> g_scores; attn zero-fill overlapped
    score_kernel<<<dim3(64, 32, 4), 256>>>(attn);
    // 2b) per-row top-30, softmax, scatter into attn, sparse ctx
    topk_kernel<<<N_TOK * NHEAD / 8, 256>>>(attn);
    // 3) output projection + residual (64x64 tiles, 256 blocks)
    oproj_kernel<<<dim3(4, 64), 256>>>(Wo, bo, query_in);
    // 4) layernorm
    ln_kernel<<<N_TOK, 256>>>(ln_g, ln_b, out);
}

// round 6
// speedup vs baseline: 3.3030x; 1.1129x over previous
#include <cuda_runtime.h>
#include <math.h>
#include <math_constants.h>

#define N_TOK 4096
#define DMODEL 256
#define NHEAD 4
#define DHEAD 64
#define TOPK 30
#define SCALE 0.25f
#define LN_EPS 1e-5f

typedef unsigned long long ull;

// ---------------- scratch (static device allocations; no runtime alloc) ----------
__device__ float g_q[N_TOK * DMODEL];
__device__ float g_k[N_TOK * DMODEL];
__device__ float g_v[N_TOK * DMODEL];
__device__ float g_ctx[N_TOK * DMODEL];
__device__ float g_resid[N_TOK * DMODEL];
__device__ float g_scores[(size_t)NHEAD * N_TOK * N_TOK];  // 256 MB score scratch

// ---------------- packed fp32x2 helpers ------------------------------------------
__device__ __forceinline__ void fma2(ull& d, ull a, ull b) {
    asm("fma.rn.f32x2 %0, %1, %2, %0;" : "+l"(d) : "l"(a), "l"(b));
}
__device__ __forceinline__ float2 unpack2(ull v) {
    float2 f;
    asm("mov.b64 {%0, %1}, %2;" : "=f"(f.x), "=f"(f.y) : "l"(v));
    return f;
}
// monotone float->uint map (ascending)
__device__ __forceinline__ unsigned ford(float f) {
    unsigned u = __float_as_uint(f);
    return (u & 0x80000000u) ? ~u : (u | 0x80000000u);
}
__device__ __forceinline__ float unford(unsigned u) {
    return __uint_as_float((u & 0x80000000u) ? (u & 0x7FFFFFFFu) : ~u);
}

// ---- warp bitonic: sort 32 ull (1/lane) DESCENDING across lanes -------------------
__device__ __forceinline__ ull bsort32_desc(ull k, int lane) {
#pragma unroll
    for (int size = 2; size <= 32; size <<= 1) {
#pragma unroll
        for (int stride = size >> 1; stride >= 1; stride >>= 1) {
            ull o = __shfl_xor_sync(0xFFFFFFFFu, k, stride);
            bool desc = ((lane & size) == 0);
            bool lower = ((lane & stride) == 0);
            bool takemax = (lower == desc);
            ull mx = (k > o) ? k : o;
            ull mn = (k > o) ? o : k;
            k = takemax ? mx : mn;
        }
    }
    return k;
}
// bitonic merge (input bitonic) -> descending
__device__ __forceinline__ ull bmerge32_desc(ull k, int lane) {
#pragma unroll
    for (int stride = 16; stride >= 1; stride >>= 1) {
        ull o = __shfl_xor_sync(0xFFFFFFFFu, k, stride);
        bool lower = ((lane & stride) == 0);
        ull mx = (k > o) ? k : o;
        ull mn = (k > o) ? o : k;
        k = lower ? mx : mn;
    }
    return k;
}

// ---------------- 64x64-tile fp32 GEMM body: C = A @ B^T (+bias)(+res) -----------
template <bool ADD_RES>
__device__ __forceinline__ void gemm64_body(const float* __restrict__ A,
                                            const float* __restrict__ B,
                                            const float* __restrict__ bias,
                                            const float* __restrict__ res,
                                            float* __restrict__ C) {
    __shared__ ull As[64 * 33];
    __shared__ ull Bs[64 * 33];
    const int tid = threadIdx.x;
    const int bm = blockIdx.y * 64;
    const int bn = blockIdx.x * 64;
    const int qg = (tid & 7) | ((tid >> 7) << 3);
    const int kg = (tid >> 3) & 15;

    ull acc[4][4];
#pragma unroll
    for (int a = 0; a < 4; ++a)
#pragma unroll
        for (int b = 0; b < 4; ++b) acc[a][b] = 0ull;

    for (int kk = 0; kk < 256; kk += 64) {
        __syncthreads();
#pragma unroll
        for (int i = 0; i < 8; ++i) {
            int idx = tid + i * 256;
            int r = idx >> 5, c = idx & 31;
            As[r * 33 + c] = *(const ull*)(A + (size_t)(bm + r) * 256 + kk + c * 2);
            Bs[r * 33 + c] = *(const ull*)(B + (size_t)(bn + r) * 256 + kk + c * 2);
        }
        __syncthreads();
#pragma unroll 8
        for (int d2 = 0; d2 < 32; ++d2) {
            ull qv[4], kv[4];
#pragma unroll
            for (int a = 0; a < 4; ++a) qv[a] = As[(qg * 4 + a) * 33 + d2];
#pragma unroll
            for (int b = 0; b < 4; ++b) kv[b] = Bs[(kg * 4 + b) * 33 + d2];
#pragma unroll
            for (int a = 0; a < 4; ++a)
#pragma unroll
                for (int b = 0; b < 4; ++b) fma2(acc[a][b], qv[a], kv[b]);
        }
    }
#pragma unroll
    for (int a = 0; a < 4; ++a) {
        int row = bm + qg * 4 + a;
#pragma unroll
        for (int b = 0; b < 4; ++b) {
            int col = bn + kg * 4 + b;
            float2 f = unpack2(acc[a][b]);
            float v = f.x + f.y + bias[col];
            if (ADD_RES) v += res[(size_t)row * 256 + col];
            C[(size_t)row * 256 + col] = v;
        }
    }
}

// ---------------- K1: fused Q/K/V projections -------------------------------------
__global__ __launch_bounds__(256) void proj_kernel(
    const float* __restrict__ q_in, const float* __restrict__ k_in,
    const float* __restrict__ v_in, const float* __restrict__ Wq,
    const float* __restrict__ bq, const float* __restrict__ Wk,
    const float* __restrict__ bk, const float* __restrict__ Wv,
    const float* __restrict__ bv) {
    const float *A, *B, *bias;
    float* C;
    if (blockIdx.z == 0) { A = q_in; B = Wq; bias = bq; C = g_q; }
    else if (blockIdx.z == 1) { A = k_in; B = Wk; bias = bk; C = g_k; }
    else { A = v_in; B = Wv; bias = bv; C = g_v; }
    gemm64_body<false>(A, B, bias, nullptr, C);
}

// ---------------- K2a: dense score GEMM -> g_scores; zero attn tile ----------------
// grid: (64 kb, 32 qb, 4 h). block 256. tile 128(q) x 64(k). micro 8x4 in ull.
__global__ __launch_bounds__(256, 2) void score_kernel(float* __restrict__ attn) {
    __shared__ ull Qs[128 * 32];
    __shared__ ull Ks[64 * 32];
    const int tid = threadIdx.x;
    const int h = blockIdx.z;
    const int qb0 = blockIdx.y * 128;
    const int kb0 = blockIdx.x * 64;
    const int kg = tid & 15;   // 16 col-groups of 4
    const int qg = tid >> 4;   // 16 row-groups of 8

    // zero-fill this block's attn tile (rows qb0..+128, cols kb0..+64), streaming
    {
        const float4 z4 = make_float4(0.f, 0.f, 0.f, 0.f);
#pragma unroll
        for (int i = 0; i < 8; ++i) {
            int idx = tid + i * 256;
            int r = idx >> 4, c4 = idx & 15;
            __stcs((float4*)(attn + (size_t)(h * N_TOK + qb0 + r) * N_TOK + kb0 +
                             c4 * 4),
                   z4);
        }
    }

    // fill Q tile: 4096 ull, swizzle c ^ (r>>3)
#pragma unroll
    for (int i = 0; i < 16; ++i) {
        int idx = tid + i * 256;
        int r = idx >> 5, c = idx & 31;
        Qs[(r << 5) | (c ^ (r >> 3))] =
            *(const ull*)(g_q + (size_t)(qb0 + r) * 256 + h * 64 + c * 2);
    }
    // fill K tile: 2048 ull, swizzle c ^ (r>>2)
#pragma unroll
    for (int i = 0; i < 8; ++i) {
        int idx = tid + i * 256;
        int r = idx >> 5, c = idx & 31;
        Ks[(r << 5) | (c ^ (r >> 2))] =
            *(const ull*)(g_k + (size_t)(kb0 + r) * 256 + h * 64 + c * 2);
    }
    __syncthreads();

    ull acc[8][4];
#pragma unroll
    for (int a = 0; a < 8; ++a)
#pragma unroll
        for (int b = 0; b < 4; ++b) acc[a][b] = 0ull;

#pragma unroll 4
    for (int d2 = 0; d2 < 32; ++d2) {
        ull qv[8], kv[4];
#pragma unroll
        for (int a = 0; a < 8; ++a) qv[a] = Qs[((qg * 8 + a) << 5) | (d2 ^ qg)];
#pragma unroll
        for (int b = 0; b < 4; ++b) kv[b] = Ks[((kg * 4 + b) << 5) | (d2 ^ kg)];
#pragma unroll
        for (int a = 0; a < 8; ++a)
#pragma unroll
            for (int b = 0; b < 4; ++b) fma2(acc[a][b], qv[a], kv[b]);
    }

#pragma unroll
    for (int a = 0; a < 8; ++a) {
        int row = qb0 + qg * 8 + a;
        float4 o;
        float2 f0 = unpack2(acc[a][0]);
        float2 f1 = unpack2(acc[a][1]);
        float2 f2 = unpack2(acc[a][2]);
        float2 f3 = unpack2(acc[a][3]);
        o.x = (f0.x + f0.y) * SCALE;
        o.y = (f1.x + f1.y) * SCALE;
        o.z = (f2.x + f2.y) * SCALE;
        o.w = (f3.x + f3.y) * SCALE;
        __stcs((float4*)(g_scores + ((size_t)(h * N_TOK + row)) * N_TOK + kb0 +
                         kg * 4),
               o);
    }
}

// ---------------- K2b: warp-per-row batched top-30 + softmax + scatter + ctx ------
// filter vs lazy tau; batch survivors; bitonic sort+merge per 32-batch.
__global__ __launch_bounds__(256) void topk_kernel(float* __restrict__ attn) {
    __shared__ ull bufs[8][64];
    const unsigned FULL = 0xFFFFFFFFu;
    const int warp = threadIdx.x >> 5, lane = threadIdx.x & 31;
    const int row = blockIdx.x * 8 + warp;  // = h*4096 + n
    const int h = row >> 12;
    const int n = row & 4095;
    const float4* p4 = (const float4*)(g_scores + (size_t)row * N_TOK);
    ull* buf = bufs[warp];

    ull L = 0ull;    // sorted desc top-32 (1/lane)
    ull tau = 0ull;  // 30th-best key so far (0 = accept all)
    int cnt = 0;     // pending candidates in buf

    for (int c = 0; c < 32; ++c) {
        float4 v = __ldcs(p4 + c * 32 + lane);
#pragma unroll
        for (int j = 0; j < 4; ++j) {
            float s = (j == 0) ? v.x : (j == 1) ? v.y : (j == 2) ? v.z : v.w;
            int col = c * 128 + lane * 4 + j;
            ull key = ((ull)ford(s) << 32) | (unsigned)(4095 - col);
            bool pred = key > tau;
            unsigned mask = __ballot_sync(FULL, pred);
            if (pred) buf[cnt + __popc(mask & ((1u << lane) - 1u))] = key;
            cnt += __popc(mask);
            if (cnt >= 32) {
                __syncwarp();
                ull C = buf[lane];
                int rem = cnt - 32;
                if (lane < rem) buf[lane] = buf[32 + lane];
                cnt = rem;
                __syncwarp();
                C = bsort32_desc(C, lane);
                ull Crev = __shfl_sync(FULL, C, 31 - lane);
                ull m = (L > Crev) ? L : Crev;
                L = bmerge32_desc(m, lane);
                tau = __shfl_sync(FULL, L, 29);
            }
        }
    }
    // final flush of leftovers (pad with 0-keys)
    {
        __syncwarp();
        ull C = (lane < cnt) ? buf[lane] : 0ull;
        C = bsort32_desc(C, lane);
        ull Crev = __shfl_sync(FULL, C, 31 - lane);
        ull m = (L > Crev) ? L : Crev;
        L = bmerge32_desc(m, lane);
    }

    // softmax over top-30 (L sorted desc; lane 0 = max)
    float val = unford((unsigned)(L >> 32));
    int idx = 4095 - (int)(L & 0xFFFFFFFFu);
    float vmax = __shfl_sync(FULL, val, 0);
    float e = (lane < TOPK) ? expf(val - vmax) : 0.f;
    float ssum = e;
#pragma unroll
    for (int o = 16; o; o >>= 1) ssum += __shfl_xor_sync(FULL, ssum, o);
    float p = e / ssum;

    // scatter the 30 probs (row already zeroed by score_kernel)
    if (lane < TOPK) attn[(size_t)row * N_TOK + idx] = p;

    // sparse ctx: ctx[n, h*64 + 2*lane .. +1] = sum_j p_j * V[idx_j]
    float2 acc = make_float2(0.f, 0.f);
    const float* vbase = g_v + h * 64 + 2 * lane;
#pragma unroll 6
    for (int j = 0; j < TOPK; ++j) {
        float pj = __shfl_sync(FULL, p, j);
        int ij = __shfl_sync(FULL, idx, j);
        float2 vv = *(const float2*)(vbase + (size_t)ij * 256);
        acc.x += pj * vv.x;
        acc.y += pj * vv.y;
    }
    *(float2*)(g_ctx + (size_t)n * 256 + h * 64 + 2 * lane) = acc;
}

// ---------------- K3: out-proj + residual -> g_resid ------------------------------
__global__ __launch_bounds__(256) void oproj_kernel(const float* __restrict__ Wo,
                                                    const float* __restrict__ bo,
                                                    const float* __restrict__ q_in) {
    gemm64_body<true>(g_ctx, Wo, bo, q_in, g_resid);
}

// ---------------- K4: row LayerNorm -> d_out[0 : N*D] -----------------------------
__global__ __launch_bounds__(256) void ln_kernel(const float* __restrict__ g,
                                                 const float* __restrict__ b,
                                                 float* __restrict__ out) {
    const int row = blockIdx.x;
    const int tid = threadIdx.x;
    float x = g_resid[(size_t)row * 256 + tid];
    float s = x, s2 = x * x;
#pragma unroll
    for (int o = 16; o; o >>= 1) {
        s += __shfl_xor_sync(0xFFFFFFFFu, s, o);
        s2 += __shfl_xor_sync(0xFFFFFFFFu, s2, o);
    }
    __shared__ float rs[8], rs2[8];
    const int w = tid >> 5, lane = tid & 31;
    if (lane == 0) { rs[w] = s; rs2[w] = s2; }
    __syncthreads();
    float tot = 0.f, tot2 = 0.f;
#pragma unroll
    for (int i = 0; i < 8; ++i) { tot += rs[i]; tot2 += rs2[i]; }
    float mu = tot * (1.0f / 256.0f);
    float var = tot2 * (1.0f / 256.0f) - mu * mu;
    float inv = rsqrtf(var + LN_EPS);
    out[(size_t)row * 256 + tid] = (x - mu) * inv * g[tid] + b[tid];
}

// ---------------- launch -----------------------------------------------------------
extern "C" void kernel_launch(void* const* d_in, const int* in_sizes, int n_in,
                              void* d_out, int out_size) {
    const float* key_in   = (const float*)d_in[0];
    const float* value_in = (const float*)d_in[1];
    const float* query_in = (const float*)d_in[2];
    const float* Wq = (const float*)d_in[3];
    const float* bq = (const float*)d_in[4];
    const float* Wk = (const float*)d_in[5];
    const float* bk = (const float*)d_in[6];
    const float* Wv = (const float*)d_in[7];
    const float* bv = (const float*)d_in[8];
    const float* Wo = (const float*)d_in[9];
    const float* bo = (const float*)d_in[10];
    const float* ln_g = (const float*)d_in[11];
    const float* ln_b = (const float*)d_in[12];

    float* out = (float*)d_out;
    float* attn = out + (size_t)N_TOK * DMODEL;

    // 1) Q/K/V projections (64x64 tiles, 768 blocks)
    proj_kernel<<<dim3(4, 64, 3), 256>>>(query_in, key_in, value_in, Wq, bq, Wk, bk,
                                         Wv, bv);
    // 2a) dense scaled scores -> g_scores; attn zero-fill overlapped
    score_kernel<<<dim3(64, 32, 4), 256>>>(attn);
    // 2b) per-row batched top-30, softmax, scatter into attn, sparse ctx
    topk_kernel<<<N_TOK * NHEAD / 8, 256>>>(attn);
    // 3) output projection + residual (64x64 tiles, 256 blocks)
    oproj_kernel<<<dim3(4, 64), 256>>>(Wo, bo, query_in);
    // 4) layernorm
    ln_kernel<<<N_TOK, 256>>>(ln_g, ln_b, out);
}